// round 11
// baseline (speedup 1.0000x reference)
#include <cuda_runtime.h>
#include <cuda_bf16.h>
#include <cstdint>

// Problem shape (fixed by dataset)
#define N_MAX   50000
#define E_MAX   800000
#define EMB     128
#define KTOT    256     // NF + EMB

// ---------------- device scratch (static: no runtime allocation) -----------
__device__ int      g_deg[N_MAX];
__device__ int      g_off[N_MAX + 1];
__device__ int      g_rank[E_MAX];
__device__ int      g_eidx[E_MAX];
__device__ uint32_t g_Ahi[N_MAX * 64];          // [N][64] bf16x2 words (hi)
__device__ uint32_t g_Alo[N_MAX * 64];          // [N][64] bf16x2 words (lo)
__device__ uint32_t g_Whi[EMB * (KTOT / 2)];    // [128][128] bf16x2 words
__device__ uint32_t g_Wlo[EMB * (KTOT / 2)];

// ===================== bf16 split helpers ==================================
__device__ __forceinline__ uint32_t pk_bf2(float lo, float hi) {
    uint32_t r;
    asm("cvt.rn.bf16x2.f32 %0, %1, %2;" : "=r"(r) : "f"(hi), "f"(lo));
    return r;
}
__device__ __forceinline__ float2 unpk_bf2(uint32_t w) {
    __nv_bfloat162 b = *reinterpret_cast<__nv_bfloat162*>(&w);
    return __bfloat1622float2(b);
}
__device__ __forceinline__ void split2(float a, float b,
                                       uint32_t& hi, uint32_t& lo) {
    hi = pk_bf2(a, b);
    float2 f = unpk_bf2(hi);
    lo = pk_bf2(a - f.x, b - f.y);
}

// ============== prep: zero degree counters + W f32->bf16 hi/lo =============
__global__ void prep_kernel(const float2* __restrict__ W2, int n) {
    int i = blockIdx.x * blockDim.x + threadIdx.x;
    if (i < n) g_deg[i] = 0;
    if (i < EMB * (KTOT / 2)) {
        float2 v = W2[i];
        uint32_t hi, lo;
        split2(v.x, v.y, hi, lo);
        g_Whi[i] = hi;
        g_Wlo[i] = lo;
    }
}

// ============================ CSR build ====================================
__global__ void hist_rank_kernel(const int* __restrict__ dst, int e) {
    int i = blockIdx.x * blockDim.x + threadIdx.x;
    if (i < e) g_rank[i] = atomicAdd(&g_deg[dst[i]], 1);
}

__global__ void scan_kernel(int n) {
    const int T = 1024;
    int tid  = threadIdx.x;
    int lane = tid & 31;
    int wid  = tid >> 5;
    int C = (n + T - 1) / T;
    int s = tid * C;
    int e = min(s + C, n);

    int sum = 0;
    for (int i = s; i < e; i++) sum += g_deg[i];

    int v = sum;
    #pragma unroll
    for (int d = 1; d < 32; d <<= 1) {
        int t = __shfl_up_sync(0xffffffffu, v, d);
        if (lane >= d) v += t;
    }
    __shared__ int wsum[32];
    if (lane == 31) wsum[wid] = v;
    __syncthreads();
    if (wid == 0) {
        int w = wsum[lane];
        #pragma unroll
        for (int d = 1; d < 32; d <<= 1) {
            int t = __shfl_up_sync(0xffffffffu, w, d);
            if (lane >= d) w += t;
        }
        wsum[lane] = w;
    }
    __syncthreads();

    int excl = (v - sum) + (wid > 0 ? wsum[wid - 1] : 0);
    int run = excl;
    for (int i = s; i < e; i++) {
        g_off[i] = run;
        run += g_deg[i];
    }
    if (e == n) g_off[n] = run;
}

__global__ void scatter_kernel(const int* __restrict__ dst, int e) {
    int i = blockIdx.x * blockDim.x + threadIdx.x;
    if (i < e) g_eidx[g_off[dst[i]] + g_rank[i]] = i;
}

// ===================== HMMA GEMM tile (one K half) ==========================
// 64 nodes x 128 cols. EPI=0: A = x (f32, split in-CTA), W half 0,
// store raw partial. EPI=1: A = pre-split aggr bf16 (copy), W half 1,
// += partial, + bias, relu.
// R7-validated fragment layout; smem rows 36 words -> conflict-free LDS.

#define GM       64
#define ROWW     36
#define SA_W     (GM * ROWW)               // 2304 words
#define SW_W     (EMB * ROWW)              // 4608 words
#define GSMEM_W  (2 * SA_W + 2 * SW_W)
#define GSMEM_B  (GSMEM_W * 4)             // 55296 B

__device__ __forceinline__ void mma_bf16(float4& d,
    uint32_t a0, uint32_t a1, uint32_t a2, uint32_t a3,
    uint32_t b0, uint32_t b1) {
    asm("mma.sync.aligned.m16n8k16.row.col.f32.bf16.bf16.f32 "
        "{%0,%1,%2,%3}, {%4,%5,%6,%7}, {%8,%9}, {%0,%1,%2,%3};"
        : "+f"(d.x), "+f"(d.y), "+f"(d.z), "+f"(d.w)
        : "r"(a0), "r"(a1), "r"(a2), "r"(a3), "r"(b0), "r"(b1));
}

template<int EPI>
__device__ __forceinline__ void gemm_tile(const float4* __restrict__ x4,
                                          const float*  __restrict__ bias,
                                          float* __restrict__ out,
                                          int n, int nb, uint32_t* sm) {
    uint32_t* sAh = sm;
    uint32_t* sAl = sm + SA_W;
    uint32_t* sWh = sm + 2 * SA_W;
    uint32_t* sWl = sm + 2 * SA_W + SW_W;

    const int koff = (EPI == 0) ? 0 : 128;

    int tid  = threadIdx.x;
    int warp = tid >> 5;
    int lane = tid & 31;
    int g    = lane >> 2;
    int tig  = lane & 3;
    int mw   = warp >> 2;
    int nw   = warp & 3;
    int m0   = mw * 32;
    int n0   = nw * 32;

    float4 acc[2][4];
    #pragma unroll
    for (int mt = 0; mt < 2; mt++)
        #pragma unroll
        for (int nt = 0; nt < 4; nt++)
            acc[mt][nt] = make_float4(0.f, 0.f, 0.f, 0.f);

    for (int kc = 0; kc < 128; kc += 64) {
        __syncthreads();
        if (EPI == 0) {
            // ---- stage A from x (f32 -> bf16 hi/lo) ----
            #pragma unroll
            for (int f = tid; f < GM * 16; f += 256) {
                int m = f >> 4;
                int q = f & 15;
                int node = nb + m;
                float4 v = make_float4(0.f, 0.f, 0.f, 0.f);
                if (node < n) v = x4[(size_t)node * 32 + (kc >> 2) + q];
                uint32_t h0, l0, h1, l1;
                split2(v.x, v.y, h0, l0);
                split2(v.z, v.w, h1, l1);
                int w = m * ROWW + q * 2;
                *reinterpret_cast<uint2*>(sAh + w) = make_uint2(h0, h1);
                *reinterpret_cast<uint2*>(sAl + w) = make_uint2(l0, l1);
            }
        } else {
            // ---- stage A from pre-split aggr (straight copy) ----
            int ko2 = kc >> 1;               // word base: 0 or 32
            #pragma unroll
            for (int f = tid; f < GM * 16; f += 256) {
                int m = f >> 4;
                int q = f & 15;
                int node = nb + m;
                uint2 h = make_uint2(0u, 0u);
                uint2 l = make_uint2(0u, 0u);
                if (node < n) {
                    size_t src = (size_t)node * 64 + ko2 + q * 2;
                    h = *reinterpret_cast<const uint2*>(g_Ahi + src);
                    l = *reinterpret_cast<const uint2*>(g_Alo + src);
                }
                int w = m * ROWW + q * 2;
                *reinterpret_cast<uint2*>(sAh + w) = h;
                *reinterpret_cast<uint2*>(sAl + w) = l;
            }
        }
        // ---- stage W chunk (pre-converted) ----
        #pragma unroll
        for (int f = tid; f < EMB * 8; f += 256) {
            int c = f >> 3;
            int q = f & 7;
            int src  = c * (KTOT / 2) + ((koff + kc) >> 1) + q * 4;
            int dstw = c * ROWW + q * 4;
            *reinterpret_cast<uint4*>(sWh + dstw) =
                *reinterpret_cast<const uint4*>(g_Whi + src);
            *reinterpret_cast<uint4*>(sWl + dstw) =
                *reinterpret_cast<const uint4*>(g_Wlo + src);
        }
        __syncthreads();

        // ---- 4 k16 steps ----
        #pragma unroll
        for (int s = 0; s < 4; s++) {
            int so = s * 8 + tig;

            uint32_t ah[2][4], al[2][4];
            #pragma unroll
            for (int mt = 0; mt < 2; mt++) {
                int r0 = (m0 + mt * 16 + g) * ROWW;
                int r1 = r0 + 8 * ROWW;
                ah[mt][0] = sAh[r0 + so];
                ah[mt][1] = sAh[r1 + so];
                ah[mt][2] = sAh[r0 + so + 4];
                ah[mt][3] = sAh[r1 + so + 4];
                al[mt][0] = sAl[r0 + so];
                al[mt][1] = sAl[r1 + so];
                al[mt][2] = sAl[r0 + so + 4];
                al[mt][3] = sAl[r1 + so + 4];
            }
            uint32_t bh[4][2], bl[4][2];
            #pragma unroll
            for (int nt = 0; nt < 4; nt++) {
                int rn = (n0 + nt * 8 + g) * ROWW;
                bh[nt][0] = sWh[rn + so];
                bh[nt][1] = sWh[rn + so + 4];
                bl[nt][0] = sWl[rn + so];
                bl[nt][1] = sWl[rn + so + 4];
            }
            #pragma unroll
            for (int mt = 0; mt < 2; mt++)
                #pragma unroll
                for (int nt = 0; nt < 4; nt++) {
                    mma_bf16(acc[mt][nt],
                             ah[mt][0], ah[mt][1], ah[mt][2], ah[mt][3],
                             bh[nt][0], bh[nt][1]);
                    mma_bf16(acc[mt][nt],
                             ah[mt][0], ah[mt][1], ah[mt][2], ah[mt][3],
                             bl[nt][0], bl[nt][1]);
                    mma_bf16(acc[mt][nt],
                             al[mt][0], al[mt][1], al[mt][2], al[mt][3],
                             bh[nt][0], bh[nt][1]);
                }
        }
    }

    // ---- epilogue ----
    #pragma unroll
    for (int mt = 0; mt < 2; mt++) {
        int r0 = nb + m0 + mt * 16 + g;
        int r1 = r0 + 8;
        #pragma unroll
        for (int nt = 0; nt < 4; nt++) {
            int col = n0 + nt * 8 + tig * 2;
            float4 a = acc[mt][nt];
            if (EPI == 1) {
                float bx = __ldg(bias + col);
                float by = __ldg(bias + col + 1);
                if (r0 < n) {
                    float* p = out + (size_t)r0 * EMB + col;
                    float2 pr = *reinterpret_cast<const float2*>(p);
                    *reinterpret_cast<float2*>(p) =
                        make_float2(fmaxf(a.x + pr.x + bx, 0.f),
                                    fmaxf(a.y + pr.y + by, 0.f));
                }
                if (r1 < n) {
                    float* p = out + (size_t)r1 * EMB + col;
                    float2 pr = *reinterpret_cast<const float2*>(p);
                    *reinterpret_cast<float2*>(p) =
                        make_float2(fmaxf(a.z + pr.x + bx, 0.f),
                                    fmaxf(a.w + pr.y + by, 0.f));
                }
            } else {
                if (r0 < n)
                    *reinterpret_cast<float2*>(out + (size_t)r0 * EMB + col) =
                        make_float2(a.x, a.y);
                if (r1 < n)
                    *reinterpret_cast<float2*>(out + (size_t)r1 * EMB + col) =
                        make_float2(a.z, a.w);
            }
        }
    }
}

// ============== mixed kernel: gather blocks + GEMM1 tiles ==================
// r % 9 == 8 -> GEMM1 tile (x @ Wx^T -> raw partial in out), else gather
// block (one warp per node, output pre-split bf16). NO occupancy cap:
// the GEMM branch needs its full register budget (R9's (256,3) cap caused
// spills and sank this structure).
__global__ void __launch_bounds__(256)
mixed_kernel(const float4* __restrict__ h4,
             const float4* __restrict__ x4,
             float* __restrict__ out, int n) {
    extern __shared__ uint32_t sm[];
    int r = blockIdx.x;

    if ((r % 9) == 8) {
        gemm_tile<0>(x4, nullptr, out, n, (r / 9) * GM, sm);
        return;
    }

    int gb   = r - r / 9;
    int warp = threadIdx.x >> 5;
    int lane = threadIdx.x & 31;
    int node = gb * 8 + warp;
    if (node >= n) return;

    int s = g_off[node];
    int e = g_off[node + 1];
    float4 a = make_float4(0.f, 0.f, 0.f, 0.f);
    int j = s;
    for (; j + 8 <= e; j += 8) {
        float4 v[8];
        #pragma unroll
        for (int u = 0; u < 8; u++) {
            int ei = __ldg(g_eidx + j + u);
            v[u] = __ldg(h4 + (size_t)ei * 32 + lane);
        }
        #pragma unroll
        for (int u = 0; u < 8; u++) {
            a.x += v[u].x; a.y += v[u].y; a.z += v[u].z; a.w += v[u].w;
        }
    }
    if (j + 4 <= e) {
        float4 v[4];
        #pragma unroll
        for (int u = 0; u < 4; u++) {
            int ei = __ldg(g_eidx + j + u);
            v[u] = __ldg(h4 + (size_t)ei * 32 + lane);
        }
        #pragma unroll
        for (int u = 0; u < 4; u++) {
            a.x += v[u].x; a.y += v[u].y; a.z += v[u].z; a.w += v[u].w;
        }
        j += 4;
    }
    for (; j < e; j++) {
        int ei = __ldg(g_eidx + j);
        float4 v0 = __ldg(h4 + (size_t)ei * 32 + lane);
        a.x += v0.x; a.y += v0.y; a.z += v0.z; a.w += v0.w;
    }

    uint32_t h0, l0, h1, l1;
    split2(a.x, a.y, h0, l0);
    split2(a.z, a.w, h1, l1);
    size_t base = (size_t)node * 64 + lane * 2;
    *reinterpret_cast<uint2*>(g_Ahi + base) = make_uint2(h0, h1);
    *reinterpret_cast<uint2*>(g_Alo + base) = make_uint2(l0, l1);
}

// ============== GEMM2: out = relu(partial + aggr @ Wh^T + b) ===============
__global__ void __launch_bounds__(256, 2)
gemm2_kernel(const float* __restrict__ bias,
             float* __restrict__ out, int n) {
    extern __shared__ uint32_t sm[];
    gemm_tile<1>(nullptr, bias, out, n, blockIdx.x * GM, sm);
}

// ---------------- launch ----------------------------------------------------
extern "C" void kernel_launch(void* const* d_in, const int* in_sizes, int n_in,
                              void* d_out, int out_size) {
    const float* h        = (const float*)d_in[0];   // [E, 128]
    const float* x        = (const float*)d_in[1];   // [N, 128]
    const int*   edge_dst = (const int*)  d_in[2];   // [E] int32
    const float* W        = (const float*)d_in[3];   // [128, 256]
    const float* b        = (const float*)d_in[4];   // [128]
    float*       out      = (float*)d_out;           // [N, 128]

    int E = in_sizes[2];
    int N = in_sizes[1] / EMB;

    cudaFuncSetAttribute(mixed_kernel,
                         cudaFuncAttributeMaxDynamicSharedMemorySize, GSMEM_B);
    cudaFuncSetAttribute(gemm2_kernel,
                         cudaFuncAttributeMaxDynamicSharedMemorySize, GSMEM_B);

    int prepN      = (N > EMB * (KTOT / 2)) ? N : EMB * (KTOT / 2);
    int gemmBlocks = (N + GM - 1) / GM;      // 782
    int combined   = gemmBlocks * 9;         // 1-in-9 are GEMM1 tiles

    prep_kernel<<<(prepN + 255) / 256, 256>>>(
        reinterpret_cast<const float2*>(W), N);
    hist_rank_kernel<<<(E + 255) / 256, 256>>>(edge_dst, E);
    scan_kernel<<<1, 1024>>>(N);
    scatter_kernel<<<(E + 255) / 256, 256>>>(edge_dst, E);
    mixed_kernel<<<combined, 256, GSMEM_B>>>(
        reinterpret_cast<const float4*>(h),
        reinterpret_cast<const float4*>(x),
        out, N);
    gemm2_kernel<<<gemmBlocks, 256, GSMEM_B>>>(b, out, N);
}

// round 12
// speedup vs baseline: 1.1722x; 1.1722x over previous
#include <cuda_runtime.h>
#include <cuda_bf16.h>
#include <cstdint>

// Problem shape (fixed by dataset)
#define N_MAX   50000
#define E_MAX   800000
#define EMB     128
#define KTOT    256     // NF + EMB

// ---------------- device scratch (static: no runtime allocation) -----------
__device__ int      g_deg[N_MAX];
__device__ int      g_off[N_MAX + 1];
__device__ int      g_rank[E_MAX];
__device__ int      g_eidx[E_MAX];
// aggr in fragment-major order: per node 128 words =
// [chunk(2)][s(4)][tig(4)][split*2+khalf(4)]
__device__ uint32_t g_Af[N_MAX * 128];
// W in fragment-major order: per out-col 256 words =
// [S(16)][tig(4)][split*2+khalf(4)]
__device__ uint32_t g_Wf[EMB * 256];

// ===================== bf16 split helpers ==================================
__device__ __forceinline__ uint32_t pk_bf2(float lo, float hi) {
    uint32_t r;
    asm("cvt.rn.bf16x2.f32 %0, %1, %2;" : "=r"(r) : "f"(hi), "f"(lo));
    return r;
}
__device__ __forceinline__ float2 unpk_bf2(uint32_t w) {
    __nv_bfloat162 b = *reinterpret_cast<__nv_bfloat162*>(&w);
    return __bfloat1622float2(b);
}
__device__ __forceinline__ void split2(float a, float b,
                                       uint32_t& hi, uint32_t& lo) {
    hi = pk_bf2(a, b);
    float2 f = unpk_bf2(hi);
    lo = pk_bf2(a - f.x, b - f.y);
}

// ============== prep: zero deg + W f32 -> fragment-major bf16 hi/lo ========
__global__ void prep_kernel(const float2* __restrict__ W2, int n) {
    int i = blockIdx.x * blockDim.x + threadIdx.x;
    if (i < n) g_deg[i] = 0;
    if (i < EMB * (KTOT / 2)) {             // 16384 k-pairs
        int c = i >> 7;                     // out col
        int p = i & 127;                    // k-pair
        float2 v = W2[i];                   // W[c][2p..2p+1]
        uint32_t hi, lo;
        split2(v.x, v.y, hi, lo);
        int w = (p >> 3) * 16 + (p & 3) * 4 + ((p >> 2) & 1);
        g_Wf[c * 256 + w]     = hi;         // split 0
        g_Wf[c * 256 + w + 2] = lo;         // split 1
    }
}

// ============================ CSR build ====================================
__global__ void hist_rank_kernel(const int* __restrict__ dst, int e) {
    int i = blockIdx.x * blockDim.x + threadIdx.x;
    if (i < e) g_rank[i] = atomicAdd(&g_deg[dst[i]], 1);
}

__global__ void scan_kernel(int n) {
    const int T = 1024;
    int tid  = threadIdx.x;
    int lane = tid & 31;
    int wid  = tid >> 5;
    int C = (n + T - 1) / T;
    int s = tid * C;
    int e = min(s + C, n);

    int sum = 0;
    for (int i = s; i < e; i++) sum += g_deg[i];

    int v = sum;
    #pragma unroll
    for (int d = 1; d < 32; d <<= 1) {
        int t = __shfl_up_sync(0xffffffffu, v, d);
        if (lane >= d) v += t;
    }
    __shared__ int wsum[32];
    if (lane == 31) wsum[wid] = v;
    __syncthreads();
    if (wid == 0) {
        int w = wsum[lane];
        #pragma unroll
        for (int d = 1; d < 32; d <<= 1) {
            int t = __shfl_up_sync(0xffffffffu, w, d);
            if (lane >= d) w += t;
        }
        wsum[lane] = w;
    }
    __syncthreads();

    int excl = (v - sum) + (wid > 0 ? wsum[wid - 1] : 0);
    int run = excl;
    for (int i = s; i < e; i++) {
        g_off[i] = run;
        run += g_deg[i];
    }
    if (e == n) g_off[n] = run;
}

__global__ void scatter_kernel(const int* __restrict__ dst, int e) {
    int i = blockIdx.x * blockDim.x + threadIdx.x;
    if (i < e) g_eidx[g_off[dst[i]] + g_rank[i]] = i;
}

// --------------------------- gather kernel ---------------------------------
// One warp per node, 16B per lane, unroll 8 for MLP. Output written in
// fragment-major bf16 hi/lo order (GEMM stages it with straight uint4 copy).
__global__ void __launch_bounds__(256)
gather_kernel(const float4* __restrict__ h4, int n) {
    int node = blockIdx.x * 8 + (threadIdx.x >> 5);
    int lane = threadIdx.x & 31;
    if (node >= n) return;

    int s = g_off[node];
    int e = g_off[node + 1];
    float4 a = make_float4(0.f, 0.f, 0.f, 0.f);
    int j = s;
    for (; j + 8 <= e; j += 8) {
        float4 v[8];
        #pragma unroll
        for (int u = 0; u < 8; u++) {
            int ei = __ldg(g_eidx + j + u);
            v[u] = __ldg(h4 + (size_t)ei * 32 + lane);
        }
        #pragma unroll
        for (int u = 0; u < 8; u++) {
            a.x += v[u].x; a.y += v[u].y; a.z += v[u].z; a.w += v[u].w;
        }
    }
    if (j + 4 <= e) {
        float4 v[4];
        #pragma unroll
        for (int u = 0; u < 4; u++) {
            int ei = __ldg(g_eidx + j + u);
            v[u] = __ldg(h4 + (size_t)ei * 32 + lane);
        }
        #pragma unroll
        for (int u = 0; u < 4; u++) {
            a.x += v[u].x; a.y += v[u].y; a.z += v[u].z; a.w += v[u].w;
        }
        j += 4;
    }
    for (; j < e; j++) {
        int ei = __ldg(g_eidx + j);
        float4 v0 = __ldg(h4 + (size_t)ei * 32 + lane);
        a.x += v0.x; a.y += v0.y; a.z += v0.z; a.w += v0.w;
    }

    // fragment-major store: pairs p0 = 2*lane, p1 = 2*lane+1 (k = 4*lane..+3)
    uint32_t h0, l0, h1, l1;
    split2(a.x, a.y, h0, l0);
    split2(a.z, a.w, h1, l1);
    size_t base = (size_t)node * 128;
    int p0    = 2 * lane;
    int chunk = p0 >> 5;
    int pp    = p0 & 31;
    int w0 = chunk * 64 + (pp >> 3) * 16 + (pp & 3) * 4 + ((pp >> 2) & 1);
    int w1 = w0 + 4;                        // pair p0+1: tig+1
    g_Af[base + w0]     = h0;
    g_Af[base + w0 + 2] = l0;
    g_Af[base + w1]     = h1;
    g_Af[base + w1 + 2] = l1;
}

// ===================== HMMA GEMM: out = relu(q @ W^T + b) ==================
// CTA = 64 nodes x 128 cols, 256 threads (8 warps: 2m x 4n, warp 32x32).
// K=256 in 4 chunks of 64. Fragment-major smem: per (row, k16 step s, tig)
// the 4 words {hi_k0, hi_k8, lo_k0, lo_k8} are one aligned LDS.128.
// Row stride 80 words -> bank-conflict-free in every phase.
// Split-precision: D += Ah*Wh + Ah*Wl + Al*Wh (fp32 accum).

#define GM       64
#define RW       80
#define SA_W     (GM * RW)                 // 5120 words
#define SW_W     (EMB * RW)                // 10240 words
#define GSMEM_W  (SA_W + SW_W + EMB)
#define GSMEM_B  (GSMEM_W * 4)             // 61952 B

__device__ __forceinline__ void mma_bf16(float4& d,
    uint32_t a0, uint32_t a1, uint32_t a2, uint32_t a3,
    uint32_t b0, uint32_t b1) {
    asm("mma.sync.aligned.m16n8k16.row.col.f32.bf16.bf16.f32 "
        "{%0,%1,%2,%3}, {%4,%5,%6,%7}, {%8,%9}, {%0,%1,%2,%3};"
        : "+f"(d.x), "+f"(d.y), "+f"(d.z), "+f"(d.w)
        : "r"(a0), "r"(a1), "r"(a2), "r"(a3), "r"(b0), "r"(b1));
}

__global__ void __launch_bounds__(256, 2)
gemm_kernel(const float4* __restrict__ x4,
            const float*  __restrict__ bias,
            float* __restrict__ out, int n) {
    extern __shared__ uint32_t sm[];
    uint32_t* sA = sm;                     // [64][80]
    uint32_t* sW = sm + SA_W;              // [128][80]
    float*    sB = reinterpret_cast<float*>(sm + SA_W + SW_W);

    int tid  = threadIdx.x;
    int warp = tid >> 5;
    int lane = tid & 31;
    int g    = lane >> 2;
    int tig  = lane & 3;
    int mw   = warp >> 2;
    int nw   = warp & 3;
    int m0   = mw * 32;
    int n0   = nw * 32;
    int nb   = blockIdx.x * GM;

    if (tid < EMB) sB[tid] = bias[tid];

    float4 acc[2][4];
    #pragma unroll
    for (int mt = 0; mt < 2; mt++)
        #pragma unroll
        for (int nt = 0; nt < 4; nt++)
            acc[mt][nt] = make_float4(0.f, 0.f, 0.f, 0.f);

    for (int kc = 0; kc < KTOT; kc += 64) {
        __syncthreads();
        if (kc < 128) {
            // ---- stage A from x: f32 -> bf16 hi/lo, fragment scatter ----
            #pragma unroll
            for (int f = tid; f < GM * 16; f += 256) {
                int m = f >> 4;
                int q = f & 15;             // float4 = pairs 2q, 2q+1
                int node = nb + m;
                float4 v = make_float4(0.f, 0.f, 0.f, 0.f);
                if (node < n) v = x4[(size_t)node * 32 + (kc >> 2) + q];
                uint32_t h0, l0, h1, l1;
                split2(v.x, v.y, h0, l0);
                split2(v.z, v.w, h1, l1);
                int p0 = 2 * q;
                int w0 = (p0 >> 3) * 16 + (p0 & 3) * 4 + ((p0 >> 2) & 1);
                int rb = m * RW;
                sA[rb + w0]         = h0;
                sA[rb + w0 + 2]     = l0;
                sA[rb + w0 + 4]     = h1;   // pair p0+1: tig+1
                sA[rb + w0 + 6]     = l1;
            }
        } else {
            // ---- stage A from pre-split fragment-major aggr: copy ----
            int cb = (kc - 128);            // 0 or 64: word base in g_Af
            #pragma unroll
            for (int f = tid; f < GM * 16; f += 256) {
                int m = f >> 4;
                int i = f & 15;
                int node = nb + m;
                uint4 v = make_uint4(0u, 0u, 0u, 0u);
                if (node < n)
                    v = *reinterpret_cast<const uint4*>(
                        g_Af + (size_t)node * 128 + cb + i * 4);
                *reinterpret_cast<uint4*>(sA + m * RW + i * 4) = v;
            }
        }
        // ---- stage W: straight copy of fragment-major columns ----
        #pragma unroll
        for (int f = tid; f < EMB * 16; f += 256) {
            int c = f >> 4;
            int i = f & 15;
            *reinterpret_cast<uint4*>(sW + c * RW + i * 4) =
                *reinterpret_cast<const uint4*>(g_Wf + c * 256 + kc + i * 4);
        }
        __syncthreads();

        // ---- 4 k16 steps, 8 LDS.128 each ----
        #pragma unroll
        for (int s = 0; s < 4; s++) {
            int wb = s * 16 + tig * 4;

            uint4 A0[2], A1[2];             // {h_k0, h_k8, l_k0, l_k8}
            #pragma unroll
            for (int mt = 0; mt < 2; mt++) {
                int r0 = (m0 + mt * 16 + g) * RW + wb;
                A0[mt] = *reinterpret_cast<const uint4*>(sA + r0);
                A1[mt] = *reinterpret_cast<const uint4*>(sA + r0 + 8 * RW);
            }
            uint4 B[4];                     // {bh0, bh1, bl0, bl1}
            #pragma unroll
            for (int nt = 0; nt < 4; nt++) {
                int rn = (n0 + nt * 8 + g) * RW + wb;
                B[nt] = *reinterpret_cast<const uint4*>(sW + rn);
            }
            #pragma unroll
            for (int mt = 0; mt < 2; mt++)
                #pragma unroll
                for (int nt = 0; nt < 4; nt++) {
                    mma_bf16(acc[mt][nt],
                             A0[mt].x, A1[mt].x, A0[mt].y, A1[mt].y,
                             B[nt].x, B[nt].y);
                    mma_bf16(acc[mt][nt],
                             A0[mt].x, A1[mt].x, A0[mt].y, A1[mt].y,
                             B[nt].z, B[nt].w);
                    mma_bf16(acc[mt][nt],
                             A0[mt].z, A1[mt].z, A0[mt].w, A1[mt].w,
                             B[nt].x, B[nt].y);
                }
        }
    }

    // ---- epilogue: bias + relu + store ----
    #pragma unroll
    for (int mt = 0; mt < 2; mt++) {
        int r0 = nb + m0 + mt * 16 + g;
        int r1 = r0 + 8;
        #pragma unroll
        for (int nt = 0; nt < 4; nt++) {
            int col = n0 + nt * 8 + tig * 2;
            float bx = sB[col], by = sB[col + 1];
            float4 a = acc[mt][nt];
            if (r0 < n) {
                float2 v = make_float2(fmaxf(a.x + bx, 0.f),
                                       fmaxf(a.y + by, 0.f));
                *reinterpret_cast<float2*>(out + (size_t)r0 * EMB + col) = v;
            }
            if (r1 < n) {
                float2 v = make_float2(fmaxf(a.z + bx, 0.f),
                                       fmaxf(a.w + by, 0.f));
                *reinterpret_cast<float2*>(out + (size_t)r1 * EMB + col) = v;
            }
        }
    }
}

// ---------------- launch ----------------------------------------------------
extern "C" void kernel_launch(void* const* d_in, const int* in_sizes, int n_in,
                              void* d_out, int out_size) {
    const float* h        = (const float*)d_in[0];   // [E, 128]
    const float* x        = (const float*)d_in[1];   // [N, 128]
    const int*   edge_dst = (const int*)  d_in[2];   // [E] int32
    const float* W        = (const float*)d_in[3];   // [128, 256]
    const float* b        = (const float*)d_in[4];   // [128]
    float*       out      = (float*)d_out;           // [N, 128]

    int E = in_sizes[2];
    int N = in_sizes[1] / EMB;

    cudaFuncSetAttribute(gemm_kernel,
                         cudaFuncAttributeMaxDynamicSharedMemorySize, GSMEM_B);

    int prepN = (N > EMB * (KTOT / 2)) ? N : EMB * (KTOT / 2);

    prep_kernel<<<(prepN + 255) / 256, 256>>>(
        reinterpret_cast<const float2*>(W), N);
    hist_rank_kernel<<<(E + 255) / 256, 256>>>(edge_dst, E);
    scan_kernel<<<1, 1024>>>(N);
    scatter_kernel<<<(E + 255) / 256, 256>>>(edge_dst, E);
    gather_kernel<<<(N + 7) / 8, 256>>>(
        reinterpret_cast<const float4*>(h), N);
    gemm_kernel<<<(N + GM - 1) / GM, 256, GSMEM_B>>>(
        reinterpret_cast<const float4*>(x), b, out, N);
}